// round 16
// baseline (speedup 1.0000x reference)
#include <cuda_runtime.h>
#include <cstdint>
#include <math_constants.h>

#define BATCH   16384
#define S       2048
#define G       256
#define NT      256
#define EPT     (S / NT)   // 8
#define LISTCAP 32
#define RANKW   1793u      // S-G+1 ascending
#define RANKL   256u       // G ascending
#define SHW     4.0f       // fixed softmax shift (winner side): exp(s - SHW)
#define SHL    -4.0f       // fixed softmax shift (loser side):  exp(SHL - s)

// ---- order-preserving float<->uint transforms (fallback path only) ----
__device__ __forceinline__ uint32_t f2u(float f) {
    uint32_t b = __float_as_uint(f);
    return b ^ ((b & 0x80000000u) ? 0xFFFFFFFFu : 0x80000000u);
}
__device__ __forceinline__ float u2f(uint32_t u) {
    uint32_t b = (u & 0x80000000u) ? (u ^ 0x80000000u) : ~u;
    return __uint_as_float(b);
}

// monotone value->bin map, 256 bins over [-4,4)
__device__ __forceinline__ int val2bin(float s) {
    int b = __float2int_rd(fmaf(s, 32.0f, 128.0f));
    return min(max(b, 0), 255);
}

// ---- block exclusive scan (u32), 256 threads ----
__device__ __forceinline__ uint32_t block_exscan_u32(uint32_t v, uint32_t* st) {
    const uint32_t full = 0xffffffffu;
    int lane = threadIdx.x & 31, w = threadIdx.x >> 5;
    uint32_t inc = v;
#pragma unroll
    for (int o = 1; o < 32; o <<= 1) {
        uint32_t t = __shfl_up_sync(full, inc, o);
        if (lane >= o) inc += t;
    }
    if (lane == 31) st[w] = inc;
    __syncthreads();
    if (threadIdx.x < 32) {
        uint32_t t = (lane < 8) ? st[lane] : 0u;
        uint32_t it = t;
#pragma unroll
        for (int o = 1; o < 8; o <<= 1) {
            uint32_t x = __shfl_up_sync(full, it, o);
            if (lane >= o) it += x;
        }
        if (lane < 8) st[lane] = it - t;
    }
    __syncthreads();
    uint32_t r = (inc - v) + st[w];
    __syncthreads();
    return r;
}

// ---- block exclusive scan (packed u64; independent halves, no cross-carry) ----
__device__ __forceinline__ unsigned long long block_exscan_u64(unsigned long long v,
                                                               unsigned long long* st) {
    const uint32_t full = 0xffffffffu;
    int lane = threadIdx.x & 31, w = threadIdx.x >> 5;
    unsigned long long inc = v;
#pragma unroll
    for (int o = 1; o < 32; o <<= 1) {
        unsigned long long t = __shfl_up_sync(full, inc, o);
        if (lane >= o) inc += t;
    }
    if (lane == 31) st[w] = inc;
    __syncthreads();
    if (threadIdx.x < 32) {
        unsigned long long t = (lane < 8) ? st[lane] : 0ull;
        unsigned long long it = t;
#pragma unroll
        for (int o = 1; o < 8; o <<= 1) {
            unsigned long long x = __shfl_up_sync(full, it, o);
            if (lane >= o) it += x;
        }
        if (lane < 8) st[lane] = it - t;
    }
    __syncthreads();
    unsigned long long r = (inc - v) + st[w];
    __syncthreads();
    return r;
}

// ---- rare fallback: exact key radix select (11/11/10 bits), one rank ----
// Elements come from the thread's own smem row slots.
__device__ uint32_t radix_one_s(const float4* sr, uint32_t rank,
                                uint32_t* hist, uint32_t* st, uint32_t* pub) {
    const int tid = threadIdx.x;
    uint32_t pfx = 0, r = rank;
#pragma unroll
    for (int rnd = 0; rnd < 3; rnd++) {
        reinterpret_cast<uint4*>(hist)[tid] = make_uint4(0, 0, 0, 0);
        reinterpret_cast<uint4*>(hist)[NT + tid] = make_uint4(0, 0, 0, 0);
        __syncthreads();
#pragma unroll
        for (int k2 = 0; k2 < 2; k2++) {
            float4 v = sr[tid + k2 * NT];
            float sv[4] = {v.x, v.y, v.z, v.w};
#pragma unroll
            for (int c = 0; c < 4; c++) {
                uint32_t u = f2u(sv[c]);
                bool ok; uint32_t bin;
                if (rnd == 0)      { ok = true;                bin = u >> 21; }
                else if (rnd == 1) { ok = (u >> 21) == pfx;    bin = (u >> 10) & 0x7FFu; }
                else               { ok = (u >> 10) == pfx;    bin = u & 0x3FFu; }
                if (ok) atomicAdd(&hist[bin], 1u);
            }
        }
        __syncthreads();
        const int nb = (rnd == 2) ? 4 : 8;
        uint32_t c[8], sum = 0;
#pragma unroll
        for (int k = 0; k < 8; k++) {
            c[k] = (k < nb) ? hist[tid * nb + k] : 0u;
            sum += c[k];
        }
        uint32_t exc = block_exscan_u32(sum, st);
        if (exc < r && r <= exc + sum) {
            uint32_t run = exc;
#pragma unroll
            for (int k = 0; k < 8; k++) {
                if (k < nb && r > run && r <= run + c[k]) {
                    pub[18] = tid * nb + k; pub[19] = r - run;
                }
                run += c[k];
            }
        }
        __syncthreads();
        uint32_t bin = pub[18]; r = pub[19];
        __syncthreads();
        pfx = (rnd == 2) ? ((pfx << 10) | bin) : ((pfx << 11) | bin);
    }
    return pfx;
}

// ---- RARE fallback: exact params for one row into dedicated smem (block-uniform) ----
__device__ void fallback_params(const float4* sr, uint32_t* hist, uint32_t* st32,
                                uint32_t* pubF, unsigned long long* fsredu, float* fsredf,
                                int tid, int lane, int wid, uint32_t* outP) {
    const uint32_t full = 0xffffffffu;
    uint32_t kW = radix_one_s(sr, RANKW, hist, st32, pubF);
    uint32_t kL = radix_one_s(sr, RANKL, hist, st32, pubF);
    float swv = u2f(kW);
    float slv = u2f(kL);
    unsigned long long packed = 0ull;
    float a2 = 0.0f, b2 = 0.0f;
#pragma unroll
    for (int k2 = 0; k2 < 2; k2++) {
        float4 v = sr[tid + k2 * NT];
        float sv[4] = {v.x, v.y, v.z, v.w};
#pragma unroll
        for (int c = 0; c < 4; c++) {
            float s = sv[c];
            bool gtW = (s > swv), eqW = (s == swv), ltL = (s < slv), eqL = (s == slv);
            float ex = __expf(gtW ? (s - SHW) : (SHL - s));
            a2 += gtW ? ex : 0.0f;
            b2 += ltL ? ex : 0.0f;
            packed += (unsigned long long)gtW
                    + ((unsigned long long)eqW << 16)
                    + ((unsigned long long)ltL << 32)
                    + ((unsigned long long)eqL << 48);
        }
    }
#pragma unroll
    for (int o = 16; o; o >>= 1) {
        packed += __shfl_xor_sync(full, packed, o);
        a2 += __shfl_xor_sync(full, a2, o);
        b2 += __shfl_xor_sync(full, b2, o);
    }
    if (lane == 0) { fsredu[wid] = packed; fsredf[wid] = a2; fsredf[8 + wid] = b2; }
    __syncthreads();
    if (tid == 0) {
        unsigned long long c = 0ull;
        float a = 0.0f, b = 0.0f;
#pragma unroll
        for (int w = 0; w < 8; w++) { c += fsredu[w]; a += fsredf[w]; b += fsredf[8 + w]; }
        outP[0] = __float_as_uint(swv);
        outP[1] = __float_as_uint(slv);
        outP[2] = __float_as_uint(a);
        outP[3] = __float_as_uint(b);
        outP[4] = (uint32_t)(c & 0xFFFFull);
        outP[5] = (uint32_t)((c >> 16) & 0xFFFFull);
        outP[6] = (uint32_t)((c >> 32) & 0xFFFFull);
        outP[7] = (uint32_t)((c >> 48) & 0xFFFFull);
    }
    __syncthreads();
}

// ---- RARE tie path for one row (contains syncs; call block-uniformly) ----
__device__ void write_tie(const float4* sr, float4* outL, float4* outSh,
                          float swv, float slv, float invW, float invL,
                          float wEq, float lEq, int eWc, int eLc,
                          unsigned long long* st64, unsigned long long* sredu, int tid) {
    uint32_t qW0 = 0, qW1 = 0, qL0 = 0, qL1 = 0;
#pragma unroll
    for (int k2 = 0; k2 < 2; k2++) {
        float4 v = sr[tid + k2 * NT];
        float sv[4] = {v.x, v.y, v.z, v.w};
#pragma unroll
        for (int c = 0; c < 4; c++) {
            uint32_t ew = (sv[c] == swv), el = (sv[c] == slv);
            if (k2 == 0) { qW0 += ew; qL0 += el; }
            else         { qW1 += ew; qL1 += el; }
        }
    }
    unsigned long long pk = (unsigned long long)qW0 | ((unsigned long long)qW1 << 16) |
                            ((unsigned long long)qL0 << 32) | ((unsigned long long)qL1 << 48);
    unsigned long long ex = block_exscan_u64(pk, st64);
    if (tid == NT - 1) sredu[7] = ex + pk;
    __syncthreads();
    unsigned long long tot = sredu[7];
    const uint32_t totW0 = (uint32_t)(tot & 0xFFFFull);
    const uint32_t totL0 = (uint32_t)((tot >> 32) & 0xFFFFull);
#pragma unroll
    for (int k = 0; k < 2; k++) {
        uint32_t beforeW = k ? totW0 + (uint32_t)((ex >> 16) & 0xFFFFull)
                             : (uint32_t)(ex & 0xFFFFull);
        uint32_t beforeL = k ? totL0 + (uint32_t)((ex >> 48) & 0xFFFFull)
                             : (uint32_t)((ex >> 32) & 0xFFFFull);
        float4 v = sr[tid + k * NT];
        float sv[4] = {v.x, v.y, v.z, v.w};
        float lw[4], sw4[4];
#pragma unroll
        for (int c = 0; c < 4; c++) {
            float s = sv[c];
            float lval = 0.0f, sval = 0.0f;
            if (s > swv) lval = __expf(s - SHW) * invW;
            else if (s == swv) { lval = (beforeW < (uint32_t)eWc) ? wEq : 0.0f; beforeW++; }
            if (s < slv) sval = __expf(SHL - s) * invL;
            else if (s == slv) { sval = (beforeL < (uint32_t)eLc) ? lEq : 0.0f; beforeL++; }
            lw[c] = lval;
            sw4[c] = sval;
        }
        outL[tid + k * NT]  = make_float4(lw[0], lw[1], lw[2], lw[3]);
        outSh[tid + k * NT] = make_float4(sw4[0], sw4[1], sw4[2], sw4[3]);
    }
    __syncthreads();   // protect scratch for a possible second tie call
}

__global__ __launch_bounds__(NT, 7)
void portfolio_kernel(const float* __restrict__ scores,
                      const float* __restrict__ short_ratio,
                      float* __restrict__ out) {
    const int row0 = blockIdx.x * 2;
    const int tid = threadIdx.x;
    const int lane = tid & 31;
    const int wid = tid >> 5;
    const uint32_t full = 0xffffffffu;

    __shared__ float4 srow[2][S / 4];               // 16 KB: both rows staged
    __shared__ __align__(16) uint32_t hist[2048];   // fast: [0,256)+[256,512); fallback: all
    __shared__ uint32_t st32[8];
    __shared__ unsigned long long st64[8];
    __shared__ uint32_t pubA[6], pubB[6], pubF[20];
    __shared__ uint32_t pubR[2][8];
    __shared__ uint32_t pub2[16];
    __shared__ uint32_t cnt4[4];
    __shared__ float lists[4][LISTCAP];   // W0, L0, W1, L1
    __shared__ float sredf[32];
    __shared__ float fsredf[16];
    __shared__ unsigned long long fsredu[8];
    __shared__ unsigned long long sredu[8];

    // ---- load both rows into SMEM, pack bins into registers ----
    const float4* rp0 = reinterpret_cast<const float4*>(scores + (size_t)row0 * S);
    const float4* rp1 = reinterpret_cast<const float4*>(scores + (size_t)(row0 + 1) * S);
    uint32_t pb0[2], pb1[2];
#pragma unroll
    for (int k = 0; k < 2; k++) {
        float4 v = rp0[tid + k * NT];
        srow[0][tid + k * NT] = v;
        pb0[k] = (uint32_t)val2bin(v.x) | ((uint32_t)val2bin(v.y) << 8) |
                 ((uint32_t)val2bin(v.z) << 16) | ((uint32_t)val2bin(v.w) << 24);
        float4 w = rp1[tid + k * NT];
        srow[1][tid + k * NT] = w;
        pb1[k] = (uint32_t)val2bin(w.x) | ((uint32_t)val2bin(w.y) << 8) |
                 ((uint32_t)val2bin(w.z) << 16) | ((uint32_t)val2bin(w.w) << 24);
    }
    hist[tid] = 0;
    hist[NT + tid] = 0;
    if (tid < 4) cnt4[tid] = 0;
    __syncthreads();

    // ---- histogram pass, both rows (register-resident packed bins; no LDS) ----
#pragma unroll
    for (int k = 0; k < EPT; k++) {
        atomicAdd(&hist[(pb0[k >> 2] >> ((k & 3) * 8)) & 0xFFu], 1u);
        atomicAdd(&hist[NT + ((pb1[k >> 2] >> ((k & 3) * 8)) & 0xFFu)], 1u);
    }
    __syncthreads();

    // ---- ONE packed scan locates both rows' ranks ----
    {
        uint32_t sa = hist[tid], sb = hist[NT + tid];
        unsigned long long e =
            block_exscan_u64((unsigned long long)sa | ((unsigned long long)sb << 32), st64);
        uint32_t ea = (uint32_t)e, eb = (uint32_t)(e >> 32);
        if (ea < RANKW && RANKW <= ea + sa) { pubA[0] = tid; pubA[1] = RANKW - ea; pubA[2] = ea + sa; }
        if (ea < RANKL && RANKL <= ea + sa) { pubA[3] = tid; pubA[4] = RANKL - ea; pubA[5] = ea; }
        if (eb < RANKW && RANKW <= eb + sb) { pubB[0] = tid; pubB[1] = RANKW - eb; pubB[2] = eb + sb; }
        if (eb < RANKL && RANKL <= eb + sb) { pubB[3] = tid; pubB[4] = RANKL - eb; pubB[5] = eb; }
        __syncthreads();
    }

    // ---- capture + coarse sums, both rows (values via own-slot LDS) ----
    float sW0c = 0.0f, sL0c = 0.0f, sW1c = 0.0f, sL1c = 0.0f;
#pragma unroll
    for (int h = 0; h < 2; h++) {
        const int binW = (int)(h ? pubB[0] : pubA[0]);
        const int binL = (int)(h ? pubB[3] : pubA[3]);
        float* listW = lists[h * 2 + 0];
        float* listL = lists[h * 2 + 1];
        uint32_t* cW = &cnt4[h * 2 + 0];
        uint32_t* cL = &cnt4[h * 2 + 1];
        float sWc = 0.0f, sLc = 0.0f;
#pragma unroll
        for (int k2 = 0; k2 < 2; k2++) {
            float4 v = srow[h][tid + k2 * NT];
            float sv[4] = {v.x, v.y, v.z, v.w};
            uint32_t pbk = h ? pb1[k2] : pb0[k2];
#pragma unroll
            for (int c = 0; c < 4; c++) {
                float s = sv[c];
                int b = (int)((pbk >> (c * 8)) & 0xFFu);
                if (b == binW) {
                    uint32_t i = atomicAdd(cW, 1u);
                    if (i < LISTCAP) listW[i] = s;
                }
                if (b == binL) {
                    uint32_t i = atomicAdd(cL, 1u);
                    if (i < LISTCAP) listL[i] = s;
                }
                bool gtB = (b > binW), ltB = (b < binL);
                float ex = __expf(gtB ? (s - SHW) : (SHL - s));
                sWc += gtB ? ex : 0.0f;
                sLc += ltB ? ex : 0.0f;
            }
        }
        if (h == 0) { sW0c = sWc; sL0c = sLc; }
        else        { sW1c = sWc; sL1c = sLc; }
    }
#pragma unroll
    for (int o = 16; o; o >>= 1) {
        sW0c += __shfl_xor_sync(full, sW0c, o);
        sL0c += __shfl_xor_sync(full, sL0c, o);
        sW1c += __shfl_xor_sync(full, sW1c, o);
        sL1c += __shfl_xor_sync(full, sL1c, o);
    }
    if (lane == 0) {
        sredf[wid] = sW0c; sredf[8 + wid] = sL0c;
        sredf[16 + wid] = sW1c; sredf[24 + wid] = sL1c;
    }
    __syncthreads();
    const bool fast0 = (cnt4[0] <= LISTCAP) && (cnt4[1] <= LISTCAP);
    const bool fast1 = (cnt4[2] <= LISTCAP) && (cnt4[3] <= LISTCAP);

    // ---- warps 0-3: sort W0/L0/W1/L1 + ballots; warps 4/5: finalize coarse sums ----
    if (wid < 4) {
        bool ok = (wid < 2) ? fast0 : fast1;
        if (ok) {
            const int side = wid & 1;   // 0 = winner side, 1 = loser side
            const uint32_t n = cnt4[wid];
            float v = ((uint32_t)lane < n) ? lists[wid][lane] : CUDART_INF_F;
#pragma unroll
            for (int k = 2; k <= 32; k <<= 1) {
#pragma unroll
                for (int j = k >> 1; j > 0; j >>= 1) {
                    float o = __shfl_xor_sync(full, v, j);
                    bool up = ((lane & k) == 0);
                    bool lower = ((lane & j) == 0);
                    float mn = fminf(v, o), mx = fmaxf(v, o);
                    v = (lower == up) ? mn : mx;
                }
            }
            uint32_t rank = (wid == 0) ? pubA[1] : (wid == 1) ? pubA[4]
                          : (wid == 2) ? pubB[1] : pubB[4];   // 1-based
            float sel = __shfl_sync(full, v, (int)(rank - 1));
            bool valid = ((uint32_t)lane < n);
            bool cmp = side ? (v < sel) : (v > sel);
            uint32_t mc = __ballot_sync(full, valid && cmp);
            uint32_t meq = __ballot_sync(full, valid && (v == sel));
            float cs = (valid && cmp) ? (side ? __expf(SHL - v) : __expf(v - SHW)) : 0.0f;
#pragma unroll
            for (int o = 16; o; o >>= 1) cs += __shfl_xor_sync(full, cs, o);
            if (lane == 0) {
                pub2[wid * 4 + 0] = __float_as_uint(sel);
                pub2[wid * 4 + 1] = __popc(mc);
                pub2[wid * 4 + 2] = __popc(meq);
                pub2[wid * 4 + 3] = __float_as_uint(cs);
            }
        }
    } else if (wid == 4) {
        float a = (lane < 8) ? sredf[lane] : 0.0f;
        float b = (lane < 8) ? sredf[8 + lane] : 0.0f;
#pragma unroll
        for (int o = 4; o; o >>= 1) {
            a += __shfl_xor_sync(full, a, o);
            b += __shfl_xor_sync(full, b, o);
        }
        if (lane == 0) { sredf[0] = a; sredf[8] = b; }
    } else if (wid == 5) {
        float a = (lane < 8) ? sredf[16 + lane] : 0.0f;
        float b = (lane < 8) ? sredf[24 + lane] : 0.0f;
#pragma unroll
        for (int o = 4; o; o >>= 1) {
            a += __shfl_xor_sync(full, a, o);
            b += __shfl_xor_sync(full, b, o);
        }
        if (lane == 0) { sredf[16] = a; sredf[24] = b; }
    }
    __syncthreads();

    // ---- RARE fallbacks (block-uniform; results into dedicated pubR) ----
    if (!fast0) fallback_params(srow[0], hist, st32, pubF, fsredu, fsredf, tid, lane, wid, pubR[0]);
    if (!fast1) fallback_params(srow[1], hist, st32, pubF, fsredu, fsredf, tid, lane, wid, pubR[1]);

    // ---- per-row epilogues (params read lazily from smem) ----
#pragma unroll
    for (int h = 0; h < 2; h++) {
        float swv, slv, sW, sL;
        int nWgt, nWeq, nLlt, nLeq;
        const bool fast = h ? fast1 : fast0;
        if (fast) {
            const uint32_t* pR = h ? pubB : pubA;
            const int base = h * 8;
            swv = __uint_as_float(pub2[base + 0]);
            slv = __uint_as_float(pub2[base + 4]);
            nWgt = (int)(S - pR[2]) + (int)pub2[base + 1];
            nWeq = (int)pub2[base + 2];
            sW = sredf[h * 16] + __uint_as_float(pub2[base + 3]);
            nLlt = (int)pR[5] + (int)pub2[base + 5];
            nLeq = (int)pub2[base + 6];
            sL = sredf[h * 16 + 8] + __uint_as_float(pub2[base + 7]);
        } else {
            const uint32_t* P = pubR[h];
            swv = __uint_as_float(P[0]); slv = __uint_as_float(P[1]);
            sW = __uint_as_float(P[2]);  sL = __uint_as_float(P[3]);
            nWgt = (int)P[4]; nWeq = (int)P[5];
            nLlt = (int)P[6]; nLeq = (int)P[7];
        }
        const int eWc = G - nWgt, eLc = G - nLlt;
        const float expWeq = __expf(swv - SHW);
        const float expLeq = __expf(SHL - slv);
        const float invW = 1.0f / (sW + (float)eWc * expWeq);
        const float invL = 1.0f / (sL + (float)eLc * expLeq);
        const float wEq = expWeq * invW, lEq = expLeq * invL;
        float4* oL = reinterpret_cast<float4*>(out + (size_t)(row0 + h) * S);
        float4* oS = reinterpret_cast<float4*>(out + (size_t)BATCH * S + (size_t)(row0 + h) * S);
        if (nWeq == eWc && nLeq == eLc) {
            // fast write: values via own-slot LDS
#pragma unroll
            for (int k = 0; k < 2; k++) {
                float4 v = srow[h][tid + k * NT];
                float sv[4] = {v.x, v.y, v.z, v.w};
                float lw[4], sw4[4];
#pragma unroll
                for (int c = 0; c < 4; c++) {
                    float s = sv[c];
                    bool gtW = (s > swv), ltL = (s < slv);
                    float ex = __expf(gtW ? (s - SHW) : (SHL - s));
                    lw[c]  = gtW ? ex * invW : ((s == swv) ? wEq : 0.0f);
                    sw4[c] = ltL ? ex * invL : ((s == slv) ? lEq : 0.0f);
                }
                oL[tid + k * NT] = make_float4(lw[0], lw[1], lw[2], lw[3]);
                oS[tid + k * NT] = make_float4(sw4[0], sw4[1], sw4[2], sw4[3]);
            }
        } else {
            write_tie(srow[h], oL, oS, swv, slv, invW, invL, wEq, lEq,
                      eWc, eLc, st64, sredu, tid);
        }
    }

    // ---- short_ratio passthrough (clipped), both rows ----
    if (tid < 2) {
        float r = short_ratio[row0 + tid];
        r = fminf(fmaxf(r, 0.0f), 1.0f);
        out[(size_t)2 * BATCH * S + row0 + tid] = r;
    }
}

extern "C" void kernel_launch(void* const* d_in, const int* in_sizes, int n_in,
                              void* d_out, int out_size) {
    const float* scores = (const float*)d_in[0];
    const float* ratio  = (const float*)d_in[1];
    if (n_in >= 2 && in_sizes[0] == BATCH && in_sizes[1] == BATCH * S) {
        const float* t = scores; scores = ratio; ratio = t;
    }
    portfolio_kernel<<<BATCH / 2, NT>>>(scores, ratio, (float*)d_out);
}